// round 12
// baseline (speedup 1.0000x reference)
#include <cuda_runtime.h>
#include <math_constants.h>

// FrechetSort: per row (B=4096, N=8192):
//   perturbed = scores - log(-log(gumbel_u))   (XLA:CPU GenerateVF32Log, aarch64-contracted)
//   action    = argsort(-perturbed)  (descending, stable)
//   log_proba = sum_r (x_r - suffix_logsumexp(x)_r),  x = scores[action]
// Output (float32): [action (B*N) | log_proba (B)]
//
// Sort: custom 4-pass 8-bit-digit LSD block radix sort over u64 kv =
// (orderkey32 << 16) | col. Warp-striped stable ranking via __match_any_sync
// + per-warp 256-bin smem histograms + one block scan per pass.

static constexpr int N_COLS  = 8192;
static constexpr int BLOCK_T = 1024;
static constexpr int ITEMS   = 8;     // 1024*8 = 8192
static constexpr int NWARP   = 32;
static constexpr int HSTRIDE = 257;   // 256 digits + 1 pad (bank decorrelation)

struct Smem {
    unsigned long long kv[N_COLS];                 // 64 KB
    union {
        unsigned int hist[NWARP * HSTRIDE];        // 32.9 KB
        float scores[N_COLS];                      // 32 KB
    } h;
    float        warp_red[NWARP];
    unsigned int scan_warp[NWARP];
};

// XLA GenerateVF32Log, aarch64 backend contraction. Positive normal x. (LOCKED — R11)
__device__ __forceinline__ float xla_vf32_logf(float xin) {
    unsigned int bits = __float_as_uint(xin);
    float e = (float)((int)(bits >> 23) - 126);
    float m = __uint_as_float((bits & 0x007fffffu) | 0x3f000000u);

    const float SQRTHF = 0.707106781186547524f;
    bool mask = m < SQRTHF;
    float tmp = mask ? m : 0.0f;
    m = __fadd_rn(m, -1.0f);
    e = __fadd_rn(e, mask ? -1.0f : 0.0f);
    m = __fadd_rn(m, tmp);

    float z = __fmul_rn(m, m);

    float y = 7.0376836292e-2f;
    y = __fmaf_rn(y, m, -1.1514610310e-1f);
    y = __fmaf_rn(y, m,  1.1676998740e-1f);
    y = __fmaf_rn(y, m, -1.2420140846e-1f);
    y = __fmaf_rn(y, m,  1.4249322787e-1f);
    y = __fmaf_rn(y, m, -1.6668057665e-1f);
    y = __fmaf_rn(y, m,  2.0000714765e-1f);
    y = __fmaf_rn(y, m, -2.4999993993e-1f);
    y = __fmaf_rn(y, m,  3.3333331174e-1f);
    y = __fmul_rn(y, m);
    y = __fmul_rn(y, z);

    y = __fmaf_rn(e, -2.12194440e-4f, y);
    m = __fmaf_rn(-0.5f, z, m);
    m = __fadd_rn(m, y);
    m = __fmaf_rn(e, 0.693359375f, m);
    return m;
}

__device__ __forceinline__ float lae(float a, float b) {
    float mx = fmaxf(a, b);
    float mn = fminf(a, b);
    if (mn == -CUDART_INF_F) return mx;
    return mx + log1pf(expf(mn - mx));
}

__global__ __launch_bounds__(BLOCK_T, 1)
void frechet_sort_kernel(const float* __restrict__ scores,
                         const float* __restrict__ gumbel_u,
                         float* __restrict__ out,
                         int n_rows, int write_logp)
{
    extern __shared__ unsigned char smem_raw[];
    Smem& sm = *reinterpret_cast<Smem*>(smem_raw);

    const int row  = blockIdx.x;
    if (row >= n_rows) return;
    const long long base = (long long)row * N_COLS;
    const int t    = threadIdx.x;
    const int lane = t & 31;
    const int warp = t >> 5;
    const unsigned FULL = 0xFFFFFFFFu;

    // ---- 1. Load (warp-striped: element e = warp*256 + j*32 + lane) + keys ----
    unsigned long long kv[ITEMS];
    #pragma unroll
    for (int j = 0; j < ITEMS; j++) {
        int e = (warp << 8) + (j << 5) + lane;
        float s = scores[base + e];
        float u = gumbel_u[base + e];
        float t1 = xla_vf32_logf(u);          // log(u)
        float t3 = xla_vf32_logf(-t1);        // log(-log(u))
        float pert = __fadd_rn(s, -t3);
        unsigned int m = __float_as_uint(pert);
        m = (m & 0x80000000u) ? ~m : (m | 0x80000000u);
        unsigned int key = ~m;                // ascending == descending pert
        kv[j] = ((unsigned long long)key << 16) | (unsigned int)e;
    }

    // ---- 2. Four 8-bit LSD passes over bits 16..47 ----
    #pragma unroll
    for (int pass = 0; pass < 4; pass++) {
        const int shift = 16 + 8 * pass;

        // zero per-warp histograms
        for (int i = t; i < NWARP * HSTRIDE; i += BLOCK_T)
            sm.h.hist[i] = 0u;
        __syncthreads();

        // warp-match ranking (stable in warp-striped element order)
        unsigned int rank_ws[ITEMS];
        #pragma unroll
        for (int j = 0; j < ITEMS; j++) {
            unsigned int dg = (unsigned int)(kv[j] >> shift) & 255u;
            unsigned int mk = __match_any_sync(FULL, dg);
            unsigned int leader = __ffs(mk) - 1u;
            unsigned int lt = __popc(mk & ((1u << lane) - 1u));
            unsigned int addr = warp * HSTRIDE + dg;
            unsigned int prev = 0u;
            if (lane == leader) {
                prev = sm.h.hist[addr];
                sm.h.hist[addr] = prev + __popc(mk);
            }
            prev = __shfl_sync(FULL, prev, leader);
            rank_ws[j] = prev + lt;
        }
        __syncthreads();

        // block exclusive scan over 8192 counters in (digit, warp) order
        {
            unsigned int v[ITEMS];
            unsigned int sum = 0u;
            #pragma unroll
            for (int k = 0; k < ITEMS; k++) {
                int i  = t * ITEMS + k;
                int w  = i & 31;
                int dg = i >> 5;
                unsigned int c = sm.h.hist[w * HSTRIDE + dg];
                v[k] = sum;         // local exclusive
                sum += c;
            }
            unsigned int incl = sum;
            #pragma unroll
            for (int off = 1; off < 32; off <<= 1) {
                unsigned int n = __shfl_up_sync(FULL, incl, off);
                if (lane >= off) incl += n;
            }
            unsigned int wexcl = incl - sum;
            if (lane == 31) sm.scan_warp[warp] = incl;
            __syncthreads();
            if (warp == 0) {
                unsigned int wv = sm.scan_warp[lane];
                unsigned int wincl = wv;
                #pragma unroll
                for (int off = 1; off < 32; off <<= 1) {
                    unsigned int n = __shfl_up_sync(FULL, wincl, off);
                    if (lane >= off) wincl += n;
                }
                sm.scan_warp[lane] = wincl - wv;
            }
            __syncthreads();
            unsigned int tbase = sm.scan_warp[warp] + wexcl;
            #pragma unroll
            for (int k = 0; k < ITEMS; k++) {
                int i  = t * ITEMS + k;
                int w  = i & 31;
                int dg = i >> 5;
                sm.h.hist[w * HSTRIDE + dg] = tbase + v[k];
            }
        }
        __syncthreads();

        // scatter
        #pragma unroll
        for (int j = 0; j < ITEMS; j++) {
            unsigned int dg = (unsigned int)(kv[j] >> shift) & 255u;
            unsigned int r  = sm.h.hist[warp * HSTRIDE + dg] + rank_ws[j];
            sm.kv[r] = kv[j];
        }
        __syncthreads();

        // gather (warp-striped)
        #pragma unroll
        for (int j = 0; j < ITEMS; j++)
            kv[j] = sm.kv[(warp << 8) + (j << 5) + lane];
        __syncthreads();
    }

    // ---- 3. Write action (rank r = warp*256 + j*32 + lane; coalesced) ----
    int idx[ITEMS];
    #pragma unroll
    for (int j = 0; j < ITEMS; j++) {
        idx[j] = (int)(kv[j] & 0xFFFFu);
        int r = (warp << 8) + (j << 5) + lane;
        out[base + r] = (float)idx[j];
    }

    if (!write_logp) return;

    // ---- 4. Stage scores in smem (hist region free now), gather x ----
    for (int i = t; i < N_COLS; i += BLOCK_T)
        sm.h.scores[i] = scores[base + i];
    __syncthreads();

    float x[ITEMS], suf[ITEMS], itot[ITEMS];
    #pragma unroll
    for (int j = 0; j < ITEMS; j++)
        x[j] = sm.h.scores[idx[j]];

    // per-item warp suffix logsumexp over lanes
    #pragma unroll
    for (int j = 0; j < ITEMS; j++) {
        float s = x[j];
        #pragma unroll
        for (int off = 1; off < 32; off <<= 1) {
            float v = __shfl_down_sync(FULL, s, off);
            if (lane + off < 32) s = lae(s, v);
        }
        suf[j] = s;                                   // lae over lanes lane..31 of item j
        itot[j] = __shfl_sync(FULL, s, 0);            // item-j total
    }

    // warp total = lae over items
    float wtot = itot[0];
    #pragma unroll
    for (int j = 1; j < ITEMS; j++) wtot = lae(wtot, itot[j]);

    // cross-warp exclusive suffix of warp totals
    if (lane == 0) sm.warp_red[warp] = wtot;
    __syncthreads();
    if (warp == 0) {
        float wv = sm.warp_red[lane];
        float wincl = wv;
        #pragma unroll
        for (int off = 1; off < 32; off <<= 1) {
            float v = __shfl_down_sync(FULL, wincl, off);
            if (lane + off < 32) wincl = lae(wincl, v);
        }
        float wexcl = __shfl_down_sync(FULL, wincl, 1);
        if (lane == 31) wexcl = -CUDART_INF_F;
        sm.warp_red[lane] = wexcl;
    }
    __syncthreads();

    // accumulate x - denom, items high rank -> low rank
    float tail = sm.warp_red[warp];   // logsumexp of all later warps
    float acc = 0.0f;
    #pragma unroll
    for (int j = ITEMS - 1; j >= 0; j--) {
        acc += x[j] - lae(suf[j], tail);
        tail = lae(tail, itot[j]);
    }

    // block reduce acc
    #pragma unroll
    for (int off = 16; off > 0; off >>= 1)
        acc += __shfl_down_sync(FULL, acc, off);
    __syncthreads();
    if (lane == 0) sm.warp_red[warp] = acc;
    __syncthreads();
    if (warp == 0) {
        float v = sm.warp_red[lane];
        #pragma unroll
        for (int off = 16; off > 0; off >>= 1)
            v += __shfl_down_sync(FULL, v, off);
        if (lane == 0)
            out[(long long)n_rows * N_COLS + row] = v;
    }
}

extern "C" void kernel_launch(void* const* d_in, const int* in_sizes, int n_in,
                              void* d_out, int out_size)
{
    const float* scores   = (const float*)d_in[0];
    const float* gumbel_u = (const float*)d_in[1];
    float* out = (float*)d_out;

    const int total = in_sizes[0];
    const int n_rows = total / N_COLS;
    const int write_logp = (out_size >= total + n_rows) ? 1 : 0;

    const size_t shbytes = sizeof(Smem);
    cudaFuncSetAttribute(frechet_sort_kernel,
                         cudaFuncAttributeMaxDynamicSharedMemorySize, (int)shbytes);

    frechet_sort_kernel<<<n_rows, BLOCK_T, shbytes>>>(scores, gumbel_u, out, n_rows, write_logp);
}

// round 13
// speedup vs baseline: 1.1875x; 1.1875x over previous
#include <cuda_runtime.h>
#include <cuda_bf16.h>
#include <cub/cub.cuh>
#include <math_constants.h>

// FrechetSort: per row (B=4096, N=8192):
//   perturbed = scores - log(-log(gumbel_u))   (XLA:CPU GenerateVF32Log, aarch64-contracted — LOCKED)
//   action    = argsort(-perturbed)  (descending, stable)
//   log_proba = sum_r (x_r - suffix_logsumexp(x)_r),  x = scores[action]
// Output (float32): [action (B*N) | log_proba (B)]
//
// Sort: cub::BlockRadixSort with RADIX_BITS=6 -> 6 digit passes over 32-bit
// keys (vs 8 passes at default 4 bits). Ranking smem ~132 KB, fits at 1 CTA/SM.

static constexpr int N_COLS  = 8192;
static constexpr int BLOCK_T = 1024;
static constexpr int ITEMS   = 8;   // 1024*8 = 8192
static constexpr int RBITS   = 6;   // 6 passes: 6+6+6+6+6+2

using BlockRadixSortT =
    cub::BlockRadixSort<unsigned int, BLOCK_T, ITEMS, unsigned short, RBITS>;

struct Smem {
    union {
        typename BlockRadixSortT::TempStorage sort;
        float scores[N_COLS];
    } u;
    float warp_red[32];
};

// XLA GenerateVF32Log, aarch64 backend contraction. Positive normal x. (LOCKED — R11)
__device__ __forceinline__ float xla_vf32_logf(float xin) {
    unsigned int bits = __float_as_uint(xin);
    float e = (float)((int)(bits >> 23) - 126);
    float m = __uint_as_float((bits & 0x007fffffu) | 0x3f000000u);

    const float SQRTHF = 0.707106781186547524f;
    bool mask = m < SQRTHF;
    float tmp = mask ? m : 0.0f;
    m = __fadd_rn(m, -1.0f);
    e = __fadd_rn(e, mask ? -1.0f : 0.0f);
    m = __fadd_rn(m, tmp);

    float z = __fmul_rn(m, m);

    float y = 7.0376836292e-2f;
    y = __fmaf_rn(y, m, -1.1514610310e-1f);
    y = __fmaf_rn(y, m,  1.1676998740e-1f);
    y = __fmaf_rn(y, m, -1.2420140846e-1f);
    y = __fmaf_rn(y, m,  1.4249322787e-1f);
    y = __fmaf_rn(y, m, -1.6668057665e-1f);
    y = __fmaf_rn(y, m,  2.0000714765e-1f);
    y = __fmaf_rn(y, m, -2.4999993993e-1f);
    y = __fmaf_rn(y, m,  3.3333331174e-1f);
    y = __fmul_rn(y, m);
    y = __fmul_rn(y, z);

    y = __fmaf_rn(e, -2.12194440e-4f, y);   // y += e*q1
    m = __fmaf_rn(-0.5f, z, m);             // m -= z*0.5  (into m — XLA association)
    m = __fadd_rn(m, y);
    m = __fmaf_rn(e, 0.693359375f, m);      // m += e*q2
    return m;
}

__device__ __forceinline__ float lae(float a, float b) {
    float mx = fmaxf(a, b);
    float mn = fminf(a, b);
    if (mn == -CUDART_INF_F) return mx;
    return mx + log1pf(expf(mn - mx));
}

__global__ __launch_bounds__(BLOCK_T, 1)
void frechet_sort_kernel(const float* __restrict__ scores,
                         const float* __restrict__ gumbel_u,
                         float* __restrict__ out,
                         int n_rows, int write_logp)
{
    extern __shared__ unsigned char smem_raw[];
    Smem& sm = *reinterpret_cast<Smem*>(smem_raw);

    const int row  = blockIdx.x;
    if (row >= n_rows) return;
    const long long base = (long long)row * N_COLS;
    const int t    = threadIdx.x;
    const int lane = t & 31;
    const int warp = t >> 5;

    // ---- 1. Load + compute keys (blocked: thread t owns [t*8, t*8+8)) ----
    unsigned int   keys[ITEMS];
    unsigned short vals[ITEMS];
    {
        const int i0 = t * ITEMS;
        const float4* s4 = reinterpret_cast<const float4*>(scores   + base + i0);
        const float4* g4 = reinterpret_cast<const float4*>(gumbel_u + base + i0);
        float s[ITEMS], g[ITEMS];
        float4 a0 = s4[0], a1 = s4[1];
        float4 b0 = g4[0], b1 = g4[1];
        s[0]=a0.x; s[1]=a0.y; s[2]=a0.z; s[3]=a0.w;
        s[4]=a1.x; s[5]=a1.y; s[6]=a1.z; s[7]=a1.w;
        g[0]=b0.x; g[1]=b0.y; g[2]=b0.z; g[3]=b0.w;
        g[4]=b1.x; g[5]=b1.y; g[6]=b1.z; g[7]=b1.w;
        #pragma unroll
        for (int j = 0; j < ITEMS; j++) {
            float t1 = xla_vf32_logf(g[j]);       // log(u)  (negative)
            float t3 = xla_vf32_logf(-t1);        // log(-log(u))
            float pert = __fadd_rn(s[j], -t3);    // scores + gumbel
            unsigned int m = __float_as_uint(pert);
            m = (m & 0x80000000u) ? ~m : (m | 0x80000000u);
            keys[j] = ~m;                         // ascending key == descending pert
            vals[j] = (unsigned short)(i0 + j);
        }
    }

    // ---- 2. Stable block radix sort (6-bit digits, 6 passes) ----
    BlockRadixSortT(sm.u.sort).Sort(keys, vals);
    __syncthreads();

    // ---- 3. Write action ----
    {
        const int r0 = t * ITEMS;
        float4 o0, o1;
        o0.x = (float)vals[0]; o0.y = (float)vals[1]; o0.z = (float)vals[2]; o0.w = (float)vals[3];
        o1.x = (float)vals[4]; o1.y = (float)vals[5]; o1.z = (float)vals[6]; o1.w = (float)vals[7];
        float4* o4 = reinterpret_cast<float4*>(out + base + r0);
        o4[0] = o0; o4[1] = o1;
    }

    if (!write_logp) return;

    // ---- 4. Stage scores in smem, gather x in rank order ----
    for (int i = t; i < N_COLS; i += BLOCK_T)
        sm.u.scores[i] = scores[base + i];
    __syncthreads();

    float x[ITEMS];
    #pragma unroll
    for (int j = 0; j < ITEMS; j++)
        x[j] = sm.u.scores[vals[j]];

    // ---- 5. Suffix logsumexp over ranks ----
    float lsuf[ITEMS];
    lsuf[ITEMS - 1] = x[ITEMS - 1];
    #pragma unroll
    for (int j = ITEMS - 2; j >= 0; j--)
        lsuf[j] = lae(x[j], lsuf[j + 1]);
    const float tot = lsuf[0];

    float incl = tot;
    #pragma unroll
    for (int off = 1; off < 32; off <<= 1) {
        float v = __shfl_down_sync(0xFFFFFFFFu, incl, off);
        if (lane + off < 32) incl = lae(incl, v);
    }
    if (lane == 0) sm.warp_red[warp] = incl;
    __syncthreads();
    if (warp == 0) {
        float wincl = sm.warp_red[lane];
        #pragma unroll
        for (int off = 1; off < 32; off <<= 1) {
            float v = __shfl_down_sync(0xFFFFFFFFu, wincl, off);
            if (lane + off < 32) wincl = lae(wincl, v);
        }
        float wexcl = __shfl_down_sync(0xFFFFFFFFu, wincl, 1);
        if (lane == 31) wexcl = -CUDART_INF_F;
        sm.warp_red[lane] = wexcl;
    }
    __syncthreads();

    float exclWithin = __shfl_down_sync(0xFFFFFFFFu, incl, 1);
    if (lane == 31) exclWithin = -CUDART_INF_F;
    const float sufExcl = lae(exclWithin, sm.warp_red[warp]);

    float acc = 0.0f;
    #pragma unroll
    for (int j = 0; j < ITEMS; j++)
        acc += x[j] - lae(lsuf[j], sufExcl);

    // ---- 6. Block reduce -> log_proba[row] ----
    #pragma unroll
    for (int off = 16; off > 0; off >>= 1)
        acc += __shfl_down_sync(0xFFFFFFFFu, acc, off);
    __syncthreads();
    if (lane == 0) sm.warp_red[warp] = acc;
    __syncthreads();
    if (warp == 0) {
        float v = sm.warp_red[lane];
        #pragma unroll
        for (int off = 16; off > 0; off >>= 1)
            v += __shfl_down_sync(0xFFFFFFFFu, v, off);
        if (lane == 0)
            out[(long long)n_rows * N_COLS + row] = v;
    }
}

extern "C" void kernel_launch(void* const* d_in, const int* in_sizes, int n_in,
                              void* d_out, int out_size)
{
    const float* scores   = (const float*)d_in[0];
    const float* gumbel_u = (const float*)d_in[1];
    float* out = (float*)d_out;

    const int total = in_sizes[0];
    const int n_rows = total / N_COLS;
    const int write_logp = (out_size >= total + n_rows) ? 1 : 0;

    const size_t shbytes = sizeof(Smem);
    cudaFuncSetAttribute(frechet_sort_kernel,
                         cudaFuncAttributeMaxDynamicSharedMemorySize, (int)shbytes);

    frechet_sort_kernel<<<n_rows, BLOCK_T, shbytes>>>(scores, gumbel_u, out, n_rows, write_logp);
}

// round 14
// speedup vs baseline: 1.4847x; 1.2503x over previous
#include <cuda_runtime.h>
#include <cuda_bf16.h>
#include <cub/cub.cuh>
#include <math_constants.h>

// FrechetSort: per row (B=4096, N=8192):
//   perturbed = scores - log(-log(gumbel_u))   (XLA:CPU GenerateVF32Log, aarch64-contracted — LOCKED)
//   action    = argsort(-perturbed)  (descending, stable)
//   log_proba = sum_r (x_r - suffix_logsumexp(x)_r),  x = scores[action]
// Output (float32): [action (B*N) | log_proba (B)]
//
// Sort: cub::BlockRadixSort keys-only over u64 kv = (key32 << 13) | col,
// begin_bit=13, end_bit=45, RADIX_BITS=4 (measured optimal). No value
// exchange phase; stability by construction (unique keys).

static constexpr int N_COLS  = 8192;
static constexpr int BLOCK_T = 1024;
static constexpr int ITEMS   = 8;    // 1024*8 = 8192
static constexpr int IDX_BITS = 13;

using BlockRadixSortT = cub::BlockRadixSort<unsigned long long, BLOCK_T, ITEMS>;

struct Smem {
    union {
        typename BlockRadixSortT::TempStorage sort;
        float scores[N_COLS];
    } u;
    float warp_red[32];
};

// XLA GenerateVF32Log, aarch64 backend contraction. Positive normal x. (LOCKED — R11)
__device__ __forceinline__ float xla_vf32_logf(float xin) {
    unsigned int bits = __float_as_uint(xin);
    float e = (float)((int)(bits >> 23) - 126);
    float m = __uint_as_float((bits & 0x007fffffu) | 0x3f000000u);

    const float SQRTHF = 0.707106781186547524f;
    bool mask = m < SQRTHF;
    float tmp = mask ? m : 0.0f;
    m = __fadd_rn(m, -1.0f);
    e = __fadd_rn(e, mask ? -1.0f : 0.0f);
    m = __fadd_rn(m, tmp);

    float z = __fmul_rn(m, m);

    float y = 7.0376836292e-2f;
    y = __fmaf_rn(y, m, -1.1514610310e-1f);
    y = __fmaf_rn(y, m,  1.1676998740e-1f);
    y = __fmaf_rn(y, m, -1.2420140846e-1f);
    y = __fmaf_rn(y, m,  1.4249322787e-1f);
    y = __fmaf_rn(y, m, -1.6668057665e-1f);
    y = __fmaf_rn(y, m,  2.0000714765e-1f);
    y = __fmaf_rn(y, m, -2.4999993993e-1f);
    y = __fmaf_rn(y, m,  3.3333331174e-1f);
    y = __fmul_rn(y, m);
    y = __fmul_rn(y, z);

    y = __fmaf_rn(e, -2.12194440e-4f, y);   // y += e*q1
    m = __fmaf_rn(-0.5f, z, m);             // m -= z*0.5  (into m — XLA association)
    m = __fadd_rn(m, y);
    m = __fmaf_rn(e, 0.693359375f, m);      // m += e*q2
    return m;
}

__device__ __forceinline__ float lae(float a, float b) {
    float mx = fmaxf(a, b);
    float mn = fminf(a, b);
    if (mn == -CUDART_INF_F) return mx;
    return mx + log1pf(expf(mn - mx));
}

__global__ __launch_bounds__(BLOCK_T, 1)
void frechet_sort_kernel(const float* __restrict__ scores,
                         const float* __restrict__ gumbel_u,
                         float* __restrict__ out,
                         int n_rows, int write_logp)
{
    extern __shared__ unsigned char smem_raw[];
    Smem& sm = *reinterpret_cast<Smem*>(smem_raw);

    const int row  = blockIdx.x;
    if (row >= n_rows) return;
    const long long base = (long long)row * N_COLS;
    const int t    = threadIdx.x;
    const int lane = t & 31;
    const int warp = t >> 5;

    // ---- 1. Load + compute packed keys (blocked: thread t owns [t*8, t*8+8)) ----
    unsigned long long keys[ITEMS];
    {
        const int i0 = t * ITEMS;
        const float4* s4 = reinterpret_cast<const float4*>(scores   + base + i0);
        const float4* g4 = reinterpret_cast<const float4*>(gumbel_u + base + i0);
        float s[ITEMS], g[ITEMS];
        float4 a0 = s4[0], a1 = s4[1];
        float4 b0 = g4[0], b1 = g4[1];
        s[0]=a0.x; s[1]=a0.y; s[2]=a0.z; s[3]=a0.w;
        s[4]=a1.x; s[5]=a1.y; s[6]=a1.z; s[7]=a1.w;
        g[0]=b0.x; g[1]=b0.y; g[2]=b0.z; g[3]=b0.w;
        g[4]=b1.x; g[5]=b1.y; g[6]=b1.z; g[7]=b1.w;
        #pragma unroll
        for (int j = 0; j < ITEMS; j++) {
            float t1 = xla_vf32_logf(g[j]);       // log(u)  (negative)
            float t3 = xla_vf32_logf(-t1);        // log(-log(u))
            float pert = __fadd_rn(s[j], -t3);    // scores + gumbel
            unsigned int m = __float_as_uint(pert);
            m = (m & 0x80000000u) ? ~m : (m | 0x80000000u);
            unsigned int k = ~m;                  // ascending key == descending pert
            keys[j] = ((unsigned long long)k << IDX_BITS) | (unsigned int)(i0 + j);
        }
    }

    // ---- 2. Keys-only stable radix sort over bits [13,45) — 8 passes, no value phase ----
    BlockRadixSortT(sm.u.sort).Sort(keys, IDX_BITS, IDX_BITS + 32);
    __syncthreads();

    // ---- 3. Extract indices + write action ----
    int idx[ITEMS];
    #pragma unroll
    for (int j = 0; j < ITEMS; j++)
        idx[j] = (int)(keys[j] & ((1u << IDX_BITS) - 1u));
    {
        const int r0 = t * ITEMS;
        float4 o0, o1;
        o0.x = (float)idx[0]; o0.y = (float)idx[1]; o0.z = (float)idx[2]; o0.w = (float)idx[3];
        o1.x = (float)idx[4]; o1.y = (float)idx[5]; o1.z = (float)idx[6]; o1.w = (float)idx[7];
        float4* o4 = reinterpret_cast<float4*>(out + base + r0);
        o4[0] = o0; o4[1] = o1;
    }

    if (!write_logp) return;

    // ---- 4. Stage scores in smem, gather x in rank order ----
    for (int i = t; i < N_COLS; i += BLOCK_T)
        sm.u.scores[i] = scores[base + i];
    __syncthreads();

    float x[ITEMS];
    #pragma unroll
    for (int j = 0; j < ITEMS; j++)
        x[j] = sm.u.scores[idx[j]];

    // ---- 5. Suffix logsumexp over ranks ----
    float lsuf[ITEMS];
    lsuf[ITEMS - 1] = x[ITEMS - 1];
    #pragma unroll
    for (int j = ITEMS - 2; j >= 0; j--)
        lsuf[j] = lae(x[j], lsuf[j + 1]);
    const float tot = lsuf[0];

    float incl = tot;
    #pragma unroll
    for (int off = 1; off < 32; off <<= 1) {
        float v = __shfl_down_sync(0xFFFFFFFFu, incl, off);
        if (lane + off < 32) incl = lae(incl, v);
    }
    if (lane == 0) sm.warp_red[warp] = incl;
    __syncthreads();
    if (warp == 0) {
        float wincl = sm.warp_red[lane];
        #pragma unroll
        for (int off = 1; off < 32; off <<= 1) {
            float v = __shfl_down_sync(0xFFFFFFFFu, wincl, off);
            if (lane + off < 32) wincl = lae(wincl, v);
        }
        float wexcl = __shfl_down_sync(0xFFFFFFFFu, wincl, 1);
        if (lane == 31) wexcl = -CUDART_INF_F;
        sm.warp_red[lane] = wexcl;
    }
    __syncthreads();

    float exclWithin = __shfl_down_sync(0xFFFFFFFFu, incl, 1);
    if (lane == 31) exclWithin = -CUDART_INF_F;
    const float sufExcl = lae(exclWithin, sm.warp_red[warp]);

    float acc = 0.0f;
    #pragma unroll
    for (int j = 0; j < ITEMS; j++)
        acc += x[j] - lae(lsuf[j], sufExcl);

    // ---- 6. Block reduce -> log_proba[row] ----
    #pragma unroll
    for (int off = 16; off > 0; off >>= 1)
        acc += __shfl_down_sync(0xFFFFFFFFu, acc, off);
    __syncthreads();
    if (lane == 0) sm.warp_red[warp] = acc;
    __syncthreads();
    if (warp == 0) {
        float v = sm.warp_red[lane];
        #pragma unroll
        for (int off = 16; off > 0; off >>= 1)
            v += __shfl_down_sync(0xFFFFFFFFu, v, off);
        if (lane == 0)
            out[(long long)n_rows * N_COLS + row] = v;
    }
}

extern "C" void kernel_launch(void* const* d_in, const int* in_sizes, int n_in,
                              void* d_out, int out_size)
{
    const float* scores   = (const float*)d_in[0];
    const float* gumbel_u = (const float*)d_in[1];
    float* out = (float*)d_out;

    const int total = in_sizes[0];
    const int n_rows = total / N_COLS;
    const int write_logp = (out_size >= total + n_rows) ? 1 : 0;

    const size_t shbytes = sizeof(Smem);
    cudaFuncSetAttribute(frechet_sort_kernel,
                         cudaFuncAttributeMaxDynamicSharedMemorySize, (int)shbytes);

    frechet_sort_kernel<<<n_rows, BLOCK_T, shbytes>>>(scores, gumbel_u, out, n_rows, write_logp);
}

// round 15
// speedup vs baseline: 1.5490x; 1.0433x over previous
#include <cuda_runtime.h>
#include <cuda_bf16.h>
#include <cub/cub.cuh>
#include <math_constants.h>

// FrechetSort: per row (B=4096, N=8192):
//   perturbed = scores - log(-log(gumbel_u))   (XLA:CPU GenerateVF32Log, aarch64-contracted — LOCKED)
//   action    = argsort(-perturbed)  (descending, stable)
//   log_proba = sum_r (x_r - suffix_logsumexp(x)_r),  x = scores[action]
// Output (float32): [action (B*N) | log_proba (B)]
//
// Sort: cub::BlockRadixSort<u32,512,16,u16> — 512 threads x 16 items,
// __launch_bounds__(512, 2) => TWO CTAs co-resident per SM to overlap
// barrier/ranking latency (prior config: 1024 thr, 1 CTA/SM, issue=48%).

static constexpr int N_COLS  = 8192;
static constexpr int BLOCK_T = 512;
static constexpr int ITEMS   = 16;   // 512*16 = 8192
static constexpr int NWARP   = BLOCK_T / 32;   // 16

using BlockRadixSortT = cub::BlockRadixSort<unsigned int, BLOCK_T, ITEMS, unsigned short>;

struct Smem {
    union {
        typename BlockRadixSortT::TempStorage sort;
        float scores[N_COLS];
    } u;
    float warp_red[NWARP];
};

// XLA GenerateVF32Log, aarch64 backend contraction. Positive normal x. (LOCKED — R11)
__device__ __forceinline__ float xla_vf32_logf(float xin) {
    unsigned int bits = __float_as_uint(xin);
    float e = (float)((int)(bits >> 23) - 126);
    float m = __uint_as_float((bits & 0x007fffffu) | 0x3f000000u);

    const float SQRTHF = 0.707106781186547524f;
    bool mask = m < SQRTHF;
    float tmp = mask ? m : 0.0f;
    m = __fadd_rn(m, -1.0f);
    e = __fadd_rn(e, mask ? -1.0f : 0.0f);
    m = __fadd_rn(m, tmp);

    float z = __fmul_rn(m, m);

    float y = 7.0376836292e-2f;
    y = __fmaf_rn(y, m, -1.1514610310e-1f);
    y = __fmaf_rn(y, m,  1.1676998740e-1f);
    y = __fmaf_rn(y, m, -1.2420140846e-1f);
    y = __fmaf_rn(y, m,  1.4249322787e-1f);
    y = __fmaf_rn(y, m, -1.6668057665e-1f);
    y = __fmaf_rn(y, m,  2.0000714765e-1f);
    y = __fmaf_rn(y, m, -2.4999993993e-1f);
    y = __fmaf_rn(y, m,  3.3333331174e-1f);
    y = __fmul_rn(y, m);
    y = __fmul_rn(y, z);

    y = __fmaf_rn(e, -2.12194440e-4f, y);   // y += e*q1
    m = __fmaf_rn(-0.5f, z, m);             // m -= z*0.5  (into m — XLA association)
    m = __fadd_rn(m, y);
    m = __fmaf_rn(e, 0.693359375f, m);      // m += e*q2
    return m;
}

__device__ __forceinline__ float lae(float a, float b) {
    float mx = fmaxf(a, b);
    float mn = fminf(a, b);
    if (mn == -CUDART_INF_F) return mx;
    return mx + log1pf(expf(mn - mx));
}

__global__ __launch_bounds__(BLOCK_T, 2)
void frechet_sort_kernel(const float* __restrict__ scores,
                         const float* __restrict__ gumbel_u,
                         float* __restrict__ out,
                         int n_rows, int write_logp)
{
    extern __shared__ unsigned char smem_raw[];
    Smem& sm = *reinterpret_cast<Smem*>(smem_raw);

    const int row  = blockIdx.x;
    if (row >= n_rows) return;
    const long long base = (long long)row * N_COLS;
    const int t    = threadIdx.x;
    const int lane = t & 31;
    const int warp = t >> 5;
    const unsigned FULL = 0xFFFFFFFFu;

    // ---- 1. Load + compute keys (blocked: thread t owns [t*16, t*16+16)) ----
    unsigned int   keys[ITEMS];
    unsigned short vals[ITEMS];
    {
        const int i0 = t * ITEMS;
        const float4* s4 = reinterpret_cast<const float4*>(scores   + base + i0);
        const float4* g4 = reinterpret_cast<const float4*>(gumbel_u + base + i0);
        #pragma unroll
        for (int q = 0; q < ITEMS / 4; q++) {
            float4 a = s4[q];
            float4 b = g4[q];
            float s[4] = {a.x, a.y, a.z, a.w};
            float g[4] = {b.x, b.y, b.z, b.w};
            #pragma unroll
            for (int c = 0; c < 4; c++) {
                int j = q * 4 + c;
                float t1 = xla_vf32_logf(g[c]);       // log(u)  (negative)
                float t3 = xla_vf32_logf(-t1);        // log(-log(u))
                float pert = __fadd_rn(s[c], -t3);    // scores + gumbel
                unsigned int m = __float_as_uint(pert);
                m = (m & 0x80000000u) ? ~m : (m | 0x80000000u);
                keys[j] = ~m;                         // ascending key == descending pert
                vals[j] = (unsigned short)(i0 + j);
            }
        }
    }

    // ---- 2. Stable block radix sort (4-bit digits, 8 passes) ----
    BlockRadixSortT(sm.u.sort).Sort(keys, vals);
    __syncthreads();

    // ---- 3. Write action (blocked: thread t owns ranks [t*16, t*16+16)) ----
    {
        const int r0 = t * ITEMS;
        float4* o4 = reinterpret_cast<float4*>(out + base + r0);
        #pragma unroll
        for (int q = 0; q < ITEMS / 4; q++) {
            float4 o;
            o.x = (float)vals[q*4+0]; o.y = (float)vals[q*4+1];
            o.z = (float)vals[q*4+2]; o.w = (float)vals[q*4+3];
            o4[q] = o;
        }
    }

    if (!write_logp) return;

    // ---- 4. Stage scores in smem, gather x in rank order ----
    for (int i = t; i < N_COLS; i += BLOCK_T)
        sm.u.scores[i] = scores[base + i];
    __syncthreads();

    float x[ITEMS];
    #pragma unroll
    for (int j = 0; j < ITEMS; j++)
        x[j] = sm.u.scores[vals[j]];

    // ---- 5. Suffix logsumexp over ranks ----
    float lsuf[ITEMS];
    lsuf[ITEMS - 1] = x[ITEMS - 1];
    #pragma unroll
    for (int j = ITEMS - 2; j >= 0; j--)
        lsuf[j] = lae(x[j], lsuf[j + 1]);
    const float tot = lsuf[0];

    // Warp inclusive suffix scan of thread totals (over 32 lanes)
    float incl = tot;
    #pragma unroll
    for (int off = 1; off < 32; off <<= 1) {
        float v = __shfl_down_sync(FULL, incl, off);
        if (lane + off < 32) incl = lae(incl, v);
    }
    if (lane == 0) sm.warp_red[warp] = incl;   // warp total
    __syncthreads();
    if (warp == 0 && lane < NWARP) {
        float wincl = sm.warp_red[lane];
        #pragma unroll
        for (int off = 1; off < NWARP; off <<= 1) {
            float v = __shfl_down_sync(0x0000FFFFu, wincl, off);
            if (lane + off < NWARP) wincl = lae(wincl, v);
        }
        float wexcl = __shfl_down_sync(0x0000FFFFu, wincl, 1);
        if (lane == NWARP - 1) wexcl = -CUDART_INF_F;
        sm.warp_red[lane] = wexcl;   // exclusive suffix of warp totals
    }
    __syncthreads();

    float exclWithin = __shfl_down_sync(FULL, incl, 1);
    if (lane == 31) exclWithin = -CUDART_INF_F;
    const float sufExcl = lae(exclWithin, sm.warp_red[warp]);

    float acc = 0.0f;
    #pragma unroll
    for (int j = 0; j < ITEMS; j++)
        acc += x[j] - lae(lsuf[j], sufExcl);

    // ---- 6. Block reduce -> log_proba[row] ----
    #pragma unroll
    for (int off = 16; off > 0; off >>= 1)
        acc += __shfl_down_sync(FULL, acc, off);
    __syncthreads();
    if (lane == 0) sm.warp_red[warp] = acc;
    __syncthreads();
    if (warp == 0 && lane < NWARP) {
        float v = sm.warp_red[lane];
        #pragma unroll
        for (int off = NWARP / 2; off > 0; off >>= 1)
            v += __shfl_down_sync(0x0000FFFFu, v, off);
        if (lane == 0)
            out[(long long)n_rows * N_COLS + row] = v;
    }
}

extern "C" void kernel_launch(void* const* d_in, const int* in_sizes, int n_in,
                              void* d_out, int out_size)
{
    const float* scores   = (const float*)d_in[0];
    const float* gumbel_u = (const float*)d_in[1];
    float* out = (float*)d_out;

    const int total = in_sizes[0];
    const int n_rows = total / N_COLS;
    const int write_logp = (out_size >= total + n_rows) ? 1 : 0;

    const size_t shbytes = sizeof(Smem);
    cudaFuncSetAttribute(frechet_sort_kernel,
                         cudaFuncAttributeMaxDynamicSharedMemorySize, (int)shbytes);

    frechet_sort_kernel<<<n_rows, BLOCK_T, shbytes>>>(scores, gumbel_u, out, n_rows, write_logp);
}

// round 16
// speedup vs baseline: 1.6679x; 1.0767x over previous
#include <cuda_runtime.h>
#include <cuda_bf16.h>
#include <cub/cub.cuh>
#include <math_constants.h>

// FrechetSort: per row (B=4096, N=8192):
//   perturbed = scores - log(-log(gumbel_u))   (XLA:CPU GenerateVF32Log, aarch64-contracted — LOCKED)
//   action    = argsort(-perturbed)  (descending, stable)
//   log_proba = sum_r (x_r - suffix_logsumexp(x)_r),  x = scores[action]
// Output (float32): [action (B*N) | log_proba (B)]
//
// Sort: cub::BlockRadixSort<u32,512,16,u16,RADIX_BITS=5> — 7 passes,
// __launch_bounds__(512, 2) => two CTAs co-resident per SM.

static constexpr int N_COLS  = 8192;
static constexpr int BLOCK_T = 512;
static constexpr int ITEMS   = 16;   // 512*16 = 8192
static constexpr int NWARP   = BLOCK_T / 32;   // 16
static constexpr int RBITS   = 5;    // 7 passes: 5*6 + 2

using BlockRadixSortT =
    cub::BlockRadixSort<unsigned int, BLOCK_T, ITEMS, unsigned short, RBITS>;

struct Smem {
    union {
        typename BlockRadixSortT::TempStorage sort;
        float scores[N_COLS];
    } u;
    float warp_red[NWARP];
};

// XLA GenerateVF32Log, aarch64 backend contraction. Positive normal x. (LOCKED — R11)
__device__ __forceinline__ float xla_vf32_logf(float xin) {
    unsigned int bits = __float_as_uint(xin);
    float e = (float)((int)(bits >> 23) - 126);
    float m = __uint_as_float((bits & 0x007fffffu) | 0x3f000000u);

    const float SQRTHF = 0.707106781186547524f;
    bool mask = m < SQRTHF;
    float tmp = mask ? m : 0.0f;
    m = __fadd_rn(m, -1.0f);
    e = __fadd_rn(e, mask ? -1.0f : 0.0f);
    m = __fadd_rn(m, tmp);

    float z = __fmul_rn(m, m);

    float y = 7.0376836292e-2f;
    y = __fmaf_rn(y, m, -1.1514610310e-1f);
    y = __fmaf_rn(y, m,  1.1676998740e-1f);
    y = __fmaf_rn(y, m, -1.2420140846e-1f);
    y = __fmaf_rn(y, m,  1.4249322787e-1f);
    y = __fmaf_rn(y, m, -1.6668057665e-1f);
    y = __fmaf_rn(y, m,  2.0000714765e-1f);
    y = __fmaf_rn(y, m, -2.4999993993e-1f);
    y = __fmaf_rn(y, m,  3.3333331174e-1f);
    y = __fmul_rn(y, m);
    y = __fmul_rn(y, z);

    y = __fmaf_rn(e, -2.12194440e-4f, y);   // y += e*q1
    m = __fmaf_rn(-0.5f, z, m);             // m -= z*0.5  (into m — XLA association)
    m = __fadd_rn(m, y);
    m = __fmaf_rn(e, 0.693359375f, m);      // m += e*q2
    return m;
}

__device__ __forceinline__ float lae(float a, float b) {
    float mx = fmaxf(a, b);
    float mn = fminf(a, b);
    if (mn == -CUDART_INF_F) return mx;
    return mx + log1pf(expf(mn - mx));
}

__global__ __launch_bounds__(BLOCK_T, 2)
void frechet_sort_kernel(const float* __restrict__ scores,
                         const float* __restrict__ gumbel_u,
                         float* __restrict__ out,
                         int n_rows, int write_logp)
{
    extern __shared__ unsigned char smem_raw[];
    Smem& sm = *reinterpret_cast<Smem*>(smem_raw);

    const int row  = blockIdx.x;
    if (row >= n_rows) return;
    const long long base = (long long)row * N_COLS;
    const int t    = threadIdx.x;
    const int lane = t & 31;
    const int warp = t >> 5;
    const unsigned FULL = 0xFFFFFFFFu;

    // ---- 1. Load + compute keys (blocked: thread t owns [t*16, t*16+16)) ----
    unsigned int   keys[ITEMS];
    unsigned short vals[ITEMS];
    {
        const int i0 = t * ITEMS;
        const float4* s4 = reinterpret_cast<const float4*>(scores   + base + i0);
        const float4* g4 = reinterpret_cast<const float4*>(gumbel_u + base + i0);
        #pragma unroll
        for (int q = 0; q < ITEMS / 4; q++) {
            float4 a = s4[q];
            float4 b = g4[q];
            float s[4] = {a.x, a.y, a.z, a.w};
            float g[4] = {b.x, b.y, b.z, b.w};
            #pragma unroll
            for (int c = 0; c < 4; c++) {
                int j = q * 4 + c;
                float t1 = xla_vf32_logf(g[c]);       // log(u)  (negative)
                float t3 = xla_vf32_logf(-t1);        // log(-log(u))
                float pert = __fadd_rn(s[c], -t3);    // scores + gumbel
                unsigned int m = __float_as_uint(pert);
                m = (m & 0x80000000u) ? ~m : (m | 0x80000000u);
                keys[j] = ~m;                         // ascending key == descending pert
                vals[j] = (unsigned short)(i0 + j);
            }
        }
    }

    // ---- 2. Stable block radix sort (5-bit digits, 7 passes) ----
    BlockRadixSortT(sm.u.sort).Sort(keys, vals);
    __syncthreads();

    // ---- 3. Write action (blocked: thread t owns ranks [t*16, t*16+16)) ----
    {
        const int r0 = t * ITEMS;
        float4* o4 = reinterpret_cast<float4*>(out + base + r0);
        #pragma unroll
        for (int q = 0; q < ITEMS / 4; q++) {
            float4 o;
            o.x = (float)vals[q*4+0]; o.y = (float)vals[q*4+1];
            o.z = (float)vals[q*4+2]; o.w = (float)vals[q*4+3];
            o4[q] = o;
        }
    }

    if (!write_logp) return;

    // ---- 4. Stage scores in smem, gather x in rank order ----
    for (int i = t; i < N_COLS; i += BLOCK_T)
        sm.u.scores[i] = scores[base + i];
    __syncthreads();

    float x[ITEMS];
    #pragma unroll
    for (int j = 0; j < ITEMS; j++)
        x[j] = sm.u.scores[vals[j]];

    // ---- 5. Suffix logsumexp over ranks ----
    float lsuf[ITEMS];
    lsuf[ITEMS - 1] = x[ITEMS - 1];
    #pragma unroll
    for (int j = ITEMS - 2; j >= 0; j--)
        lsuf[j] = lae(x[j], lsuf[j + 1]);
    const float tot = lsuf[0];

    // Warp inclusive suffix scan of thread totals (over 32 lanes)
    float incl = tot;
    #pragma unroll
    for (int off = 1; off < 32; off <<= 1) {
        float v = __shfl_down_sync(FULL, incl, off);
        if (lane + off < 32) incl = lae(incl, v);
    }
    if (lane == 0) sm.warp_red[warp] = incl;   // warp total
    __syncthreads();
    if (warp == 0 && lane < NWARP) {
        float wincl = sm.warp_red[lane];
        #pragma unroll
        for (int off = 1; off < NWARP; off <<= 1) {
            float v = __shfl_down_sync(0x0000FFFFu, wincl, off);
            if (lane + off < NWARP) wincl = lae(wincl, v);
        }
        float wexcl = __shfl_down_sync(0x0000FFFFu, wincl, 1);
        if (lane == NWARP - 1) wexcl = -CUDART_INF_F;
        sm.warp_red[lane] = wexcl;   // exclusive suffix of warp totals
    }
    __syncthreads();

    float exclWithin = __shfl_down_sync(FULL, incl, 1);
    if (lane == 31) exclWithin = -CUDART_INF_F;
    const float sufExcl = lae(exclWithin, sm.warp_red[warp]);

    float acc = 0.0f;
    #pragma unroll
    for (int j = 0; j < ITEMS; j++)
        acc += x[j] - lae(lsuf[j], sufExcl);

    // ---- 6. Block reduce -> log_proba[row] ----
    #pragma unroll
    for (int off = 16; off > 0; off >>= 1)
        acc += __shfl_down_sync(FULL, acc, off);
    __syncthreads();
    if (lane == 0) sm.warp_red[warp] = acc;
    __syncthreads();
    if (warp == 0 && lane < NWARP) {
        float v = sm.warp_red[lane];
        #pragma unroll
        for (int off = NWARP / 2; off > 0; off >>= 1)
            v += __shfl_down_sync(0x0000FFFFu, v, off);
        if (lane == 0)
            out[(long long)n_rows * N_COLS + row] = v;
    }
}

extern "C" void kernel_launch(void* const* d_in, const int* in_sizes, int n_in,
                              void* d_out, int out_size)
{
    const float* scores   = (const float*)d_in[0];
    const float* gumbel_u = (const float*)d_in[1];
    float* out = (float*)d_out;

    const int total = in_sizes[0];
    const int n_rows = total / N_COLS;
    const int write_logp = (out_size >= total + n_rows) ? 1 : 0;

    const size_t shbytes = sizeof(Smem);
    cudaFuncSetAttribute(frechet_sort_kernel,
                         cudaFuncAttributeMaxDynamicSharedMemorySize, (int)shbytes);

    frechet_sort_kernel<<<n_rows, BLOCK_T, shbytes>>>(scores, gumbel_u, out, n_rows, write_logp);
}